// round 8
// baseline (speedup 1.0000x reference)
#include <cuda_runtime.h>

#define FULLMASK 0xffffffffu
constexpr int Bn = 2048;
constexpr int Sn = 2048;
constexpr int K  = 20;     // taps for E-FIR / G prefix
constexpr int KS = 12;     // sigma-feedback taps in scan
constexpr int LCH = 64;    // stored steps per chunk (32 chunks/row)
constexpr int NCH = Sn / LCH;
constexpr float LOG2E = 1.4426950408889634f;
constexpr float LN2   = 0.6931471805599453f;

__device__ float g_alpha[K];
__device__ float g_beta[K];                   // pre-scaled by LOG2E
__device__ float g_gam[K + 1];                // prefix sums incl fcb

// ============================================================
// Kernel A: coefficients. Whh staged through smem (coalesced LDG.128),
// then W columns into registers. 19 serial power iterations.
// ============================================================
__global__ void __launch_bounds__(128) coef_kernel(
        const float* __restrict__ Wih, const float* __restrict__ Bih,
        const float* __restrict__ Whh, const float* __restrict__ Bhh,
        const float* __restrict__ Fcw, const float* __restrict__ Fcb) {
    __shared__ __align__(16) float Ws[64 * 64];
    __shared__ __align__(16) float P[K][64];
    __shared__ __align__(16) float pcur[64];
    __shared__ float red[128];
    __shared__ float uvb[3][64];
    __shared__ float sg[K];
    const int td = threadIdx.x;
    const int j  = td & 63;
    const int h  = td >> 6;

    // coalesced stage of Whh
    #pragma unroll
    for (int m = 0; m < 8; ++m)
        reinterpret_cast<float4*>(Ws)[td + 128 * m] =
            reinterpret_cast<const float4*>(Whh)[td + 128 * m];
    if (h == 0) {
        uvb[0][j] = Wih[2 * j];
        uvb[1][j] = Wih[2 * j + 1];
        uvb[2][j] = Bih[j] + Bhh[j];
        float f = Fcw[j];
        P[0][j] = f;
        pcur[j] = f;
    }
    __syncthreads();

    float Wreg[32];                  // Wreg[r] = Whh[32h+r][j]  (from smem, no conflicts)
    #pragma unroll
    for (int r = 0; r < 32; ++r) Wreg[r] = Ws[(32 * h + r) * 64 + j];

    #pragma unroll 1
    for (int k = 1; k < K; ++k) {
        const float4* pp = reinterpret_cast<const float4*>(pcur) + 8 * h;
        float a0 = 0.f, a1 = 0.f, a2 = 0.f, a3 = 0.f;
        #pragma unroll
        for (int m = 0; m < 8; ++m) {
            float4 q = pp[m];                    // broadcast LDS.128
            a0 = fmaf(Wreg[4 * m + 0], q.x, a0);
            a1 = fmaf(Wreg[4 * m + 1], q.y, a1);
            a2 = fmaf(Wreg[4 * m + 2], q.z, a2);
            a3 = fmaf(Wreg[4 * m + 3], q.w, a3);
        }
        red[td] = (a0 + a1) + (a2 + a3);
        __syncthreads();
        if (h == 0) {
            float np = red[j] + red[64 + j];
            P[k][j] = np;
            pcur[j] = np;
        }
        __syncthreads();
    }

    if (td < K) {                    // one k per thread: 3 dots of length 64
        const float* Pk = P[td];
        float A = 0.f, B = 0.f, C = 0.f;
        #pragma unroll 8
        for (int m = 0; m < 64; ++m) {
            int jj = (m + td) & 63;
            float p = Pk[jj];
            A = fmaf(p, uvb[0][jj], A);
            B = fmaf(p, uvb[1][jj], B);
            C = fmaf(p, uvb[2][jj], C);
        }
        g_alpha[td] = A;
        g_beta[td]  = B * LOG2E;
        sg[td] = C;
    }
    __syncthreads();
    if (td == 0) {
        float acc = Fcb[0];
        g_gam[0] = acc;
        #pragma unroll 1
        for (int k = 0; k < K; ++k) { acc += sg[k]; g_gam[k + 1] = acc; }
    }
}

// ============================================================
// Kernel B (fused): one block per row.
//  P1: stage res^2 in smem + unbiased variance -> sigma0
//  P2: K-tap FIR + G fold -> E in smem (never touches global)
//  P3: warp 0 runs 32 chunk-scans (LCH=64, warm-up 63) -> out
// ============================================================
__global__ void __launch_bounds__(256) fused_kernel(const float* __restrict__ res,
                                                    float* __restrict__ out) {
    __shared__ __align__(16) float xs[31 + Sn + 9];
    __shared__ __align__(16) float E_s[Sn + 32];
    __shared__ float sal[K];
    __shared__ float sgam[K + 1];
    __shared__ float sbeta[KS];
    __shared__ float rsum[8], rsq[8];
    __shared__ float svar;
    const int b  = blockIdx.x;
    const int td = threadIdx.x;
    const float* r = res + (size_t)b * Sn;
    float* orow = out + (size_t)b * Sn;

    if (td < 31)     xs[td] = 0.f;
    if (td < K)      sal[td] = g_alpha[td];
    if (td < K + 1)  sgam[td] = g_gam[td];
    if (td < KS)     sbeta[td] = g_beta[td];
    if (td < 9)      xs[31 + Sn + td] = 0.f;
    if (td >= 224)   E_s[Sn + (td - 224)] = 0.f;

    // ---- P1: stage x^2 + variance ----
    float sum = 0.f, sq = 0.f;
    #pragma unroll
    for (int i = td; i < Sn / 4; i += 256) {
        float4 q = reinterpret_cast<const float4*>(r)[i];
        xs[31 + 4 * i + 0] = q.x * q.x;
        xs[31 + 4 * i + 1] = q.y * q.y;
        xs[31 + 4 * i + 2] = q.z * q.z;
        xs[31 + 4 * i + 3] = q.w * q.w;
        sum += (q.x + q.y) + (q.z + q.w);
        sq = fmaf(q.x, q.x, sq); sq = fmaf(q.y, q.y, sq);
        sq = fmaf(q.z, q.z, sq); sq = fmaf(q.w, q.w, sq);
    }
    #pragma unroll
    for (int o = 16; o; o >>= 1) {
        sum += __shfl_xor_sync(FULLMASK, sum, o);
        sq  += __shfl_xor_sync(FULLMASK, sq, o);
    }
    if ((td & 31) == 0) { rsum[td >> 5] = sum; rsq[td >> 5] = sq; }
    __syncthreads();
    if (td == 0) {
        float S = 0.f, Q = 0.f;
        #pragma unroll
        for (int w = 0; w < 8; ++w) { S += rsum[w]; Q += rsq[w]; }
        float v = (Q - S * S * (1.f / Sn)) * (1.f / (Sn - 1));
        svar = v;
        orow[0] = v;
    }

    // ---- P2: FIR into E_s (i = t-1) ----
    const int i0 = td * 8;
    float w[40];
    #pragma unroll
    for (int m = 0; m < 10; ++m)
        reinterpret_cast<float4*>(w)[m] = *reinterpret_cast<const float4*>(&xs[i0 + 4 * m]);
    float acc[8] = {0.f, 0.f, 0.f, 0.f, 0.f, 0.f, 0.f, 0.f};
    #pragma unroll
    for (int k = 0; k < K; ++k) {
        float a = sal[k];
        #pragma unroll
        for (int i = 0; i < 8; ++i) acc[i] = fmaf(a, w[i + 31 - k], acc[i]);
    }
    #pragma unroll
    for (int i = 0; i < 8; ++i) {
        int t = i0 + i + 1;
        acc[i] = (acc[i] + sgam[min(t, K)]) * LOG2E;
    }
    reinterpret_cast<float4*>(E_s + i0)[0] = make_float4(acc[0], acc[1], acc[2], acc[3]);
    reinterpret_cast<float4*>(E_s + i0)[1] = make_float4(acc[4], acc[5], acc[6], acc[7]);
    __syncthreads();

    // ---- P3: chunk scans (warp 0 only; chunk c = lane) ----
    if (td < 32) {
        const int c = td;
        float beta[KS];
        #pragma unroll
        for (int k = 0; k < KS; ++k) beta[k] = sbeta[k];

        const int t_start = (c == 0) ? 1 : (c * LCH - 63);   // === 1 (mod 16)
        const int nb = (c == 0) ? (LCH / 16) : (LCH / 16 + 4);
        const int qlo = c * LCH;
        const int qhi = c * LCH + LCH;

        float hist[16];
        #pragma unroll
        for (int i = 0; i < 16; ++i) hist[i] = 0.f;
        float sigma = 0.f;
        float q0 = 0.f, q1 = 0.f, q2 = 0.f, q3 = 0.f;
        if (c == 0) { sigma = svar; hist[0] = sigma; q0 = sigma; }

        #pragma unroll 1
        for (int blk = 0; blk < nb; ++blk) {
            const int tb = t_start + 16 * blk;
            const float4* ep = reinterpret_cast<const float4*>(E_s + (tb - 1));
            float4 ea = ep[0], eb4 = ep[1], ec = ep[2], ed = ep[3];
            float ecur[16] = {ea.x, ea.y, ea.z, ea.w, eb4.x, eb4.y, eb4.z, eb4.w,
                              ec.x, ec.y, ec.z, ec.w, ed.x, ed.y, ed.z, ed.w};
            #pragma unroll
            for (int ss = 0; ss < 16; ++ss) {
                const int t = tb + ss;                   // t === 1+ss (mod 16)
                float p0 = 0.f, p1 = 0.f, p2 = 0.f, p3 = ecur[ss];
                #pragma unroll
                for (int k = 1; k < KS; k += 4) p0 = fmaf(beta[k], hist[(ss - k) & 15], p0);
                #pragma unroll
                for (int k = 2; k < KS; k += 4) p1 = fmaf(beta[k], hist[(ss - k) & 15], p1);
                #pragma unroll
                for (int k = 3; k < KS; k += 4) p2 = fmaf(beta[k], hist[(ss - k) & 15], p2);
                #pragma unroll
                for (int k = 4; k < KS; k += 4) p3 = fmaf(beta[k], hist[(ss - k) & 15], p3);
                float rest = (p0 + p1) + (p2 + p3);
                float y = fmaf(beta[0], sigma, rest);    // y = x * log2(e)
                float e;
                asm("ex2.approx.f32 %0, %1;" : "=f"(e) : "f"(y));
                float lg;
                asm("lg2.approx.f32 %0, %1;" : "=f"(lg) : "f"(e + 1.0f));
                sigma = fmaf(lg, LN2, 1e-6f);            // softplus(x) + EPS
                hist[(1 + ss) & 15] = sigma;
                const int tm4 = (1 + ss) & 3;            // compile-time
                if (tm4 == 0)      q0 = sigma;
                else if (tm4 == 1) q1 = sigma;
                else if (tm4 == 2) q2 = sigma;
                else {
                    q3 = sigma;
                    if (t - 3 >= qlo && t < qhi)
                        *reinterpret_cast<float4*>(orow + (t - 3)) =
                            make_float4(q0, q1, q2, q3);
                }
            }
        }
    }
}

extern "C" void kernel_launch(void* const* d_in, const int* in_sizes, int n_in,
                              void* d_out, int out_size) {
    (void)in_sizes; (void)n_in; (void)out_size;
    const float* res = (const float*)d_in[0];
    const float* Wih = (const float*)d_in[1];
    const float* Bih = (const float*)d_in[2];
    const float* Whh = (const float*)d_in[3];
    const float* Bhh = (const float*)d_in[4];
    const float* Fcw = (const float*)d_in[5];
    const float* Fcb = (const float*)d_in[6];
    float* out = (float*)d_out;

    coef_kernel<<<1, 128>>>(Wih, Bih, Whh, Bhh, Fcw, Fcb);
    fused_kernel<<<Bn, 256>>>(res, out);
}

// round 9
// speedup vs baseline: 1.0557x; 1.0557x over previous
#include <cuda_runtime.h>

#define FULLMASK 0xffffffffu
constexpr int Bn = 2048;
constexpr int Sn = 2048;
constexpr int K  = 20;     // taps for E-FIR / G prefix
constexpr int KS = 12;     // sigma-feedback taps in scan
constexpr int CCH = 16;    // time chunks per row
constexpr int LCH = 128;   // stored steps per chunk
constexpr int WUP = 63;    // warm-up steps
constexpr float LOG2E = 1.4426950408889634f;
constexpr float LN2   = 0.6931471805599453f;

// ---- static scratch ----
__device__ float g_E[(size_t)Bn * Sn + 64];
__device__ float g_alpha[K];
__device__ float g_beta[K];                   // pre-scaled by LOG2E
__device__ float g_gam[K + 1];                // prefix sums incl fcb
__device__ volatile int g_flag;               // 0 at load; reset each launch
__device__ int g_passed;

// ============================================================
// Kernel 1 (fir + embedded coef):
//  block 0: coef (19 power iters, 256 threads) -> flag -> own P1/P2
//  blocks >0: P1 (variance, x^2 stage) -> spin flag -> P2 (FIR -> g_E)
// ============================================================
__global__ void __launch_bounds__(256) fir_kernel(
        const float* __restrict__ res,
        const float* __restrict__ Wih, const float* __restrict__ Bih,
        const float* __restrict__ Whh, const float* __restrict__ Bhh,
        const float* __restrict__ Fcw, const float* __restrict__ Fcb,
        float* __restrict__ out) {
    // uni: Ws (16KB) during block-0 coef; xs (x^2 window) during P1/P2
    __shared__ __align__(16) float uni[4096];
    __shared__ __align__(16) float P[K][64];
    __shared__ __align__(16) float pcur[64];
    __shared__ float red[256];
    __shared__ float uvb[3][64];
    __shared__ float sg[K];
    __shared__ float sal[K];
    __shared__ float sgam[K + 1];
    __shared__ float rsum[8], rsq[8];

    const int b  = blockIdx.x;
    const int td = threadIdx.x;
    const float* r = res + (size_t)b * Sn;

    // ---------- block 0: coefficients ----------
    if (b == 0) {
        // stage Whh coalesced into uni (4096 floats)
        #pragma unroll
        for (int m = 0; m < 4; ++m)
            reinterpret_cast<float4*>(uni)[td + 256 * m] =
                reinterpret_cast<const float4*>(Whh)[td + 256 * m];
        const int j = td & 63;
        const int h = td >> 6;                 // 0..3 -> rows 16h..16h+15
        if (h == 0) {
            uvb[0][j] = Wih[2 * j];
            uvb[1][j] = Wih[2 * j + 1];
            uvb[2][j] = Bih[j] + Bhh[j];
            float f = Fcw[j];
            P[0][j] = f;
            pcur[j] = f;
        }
        __syncthreads();

        float Wreg[16];                        // Wreg[r] = Whh[16h+r][j]
        #pragma unroll
        for (int rr = 0; rr < 16; ++rr) Wreg[rr] = uni[(16 * h + rr) * 64 + j];

        #pragma unroll 1
        for (int k = 1; k < K; ++k) {
            const float4* pp = reinterpret_cast<const float4*>(pcur) + 4 * h;
            float a0 = 0.f, a1 = 0.f, a2 = 0.f, a3 = 0.f;
            #pragma unroll
            for (int m = 0; m < 4; ++m) {
                float4 q = pp[m];              // broadcast LDS.128
                a0 = fmaf(Wreg[4 * m + 0], q.x, a0);
                a1 = fmaf(Wreg[4 * m + 1], q.y, a1);
                a2 = fmaf(Wreg[4 * m + 2], q.z, a2);
                a3 = fmaf(Wreg[4 * m + 3], q.w, a3);
            }
            red[td] = (a0 + a1) + (a2 + a3);
            __syncthreads();
            if (h == 0) {
                float np = (red[j] + red[64 + j]) + (red[128 + j] + red[192 + j]);
                P[k][j] = np;
                pcur[j] = np;
            }
            __syncthreads();
        }

        if (td < K) {                          // 3 dots of length 64, skewed
            const float* Pk = P[td];
            float A = 0.f, B = 0.f, C = 0.f;
            #pragma unroll 8
            for (int m = 0; m < 64; ++m) {
                int jj = (m + td) & 63;
                float p = Pk[jj];
                A = fmaf(p, uvb[0][jj], A);
                B = fmaf(p, uvb[1][jj], B);
                C = fmaf(p, uvb[2][jj], C);
            }
            g_alpha[td] = A;
            g_beta[td]  = B * LOG2E;
            sg[td] = C;
        }
        __syncthreads();
        if (td == 0) {
            float acc = Fcb[0];
            g_gam[0] = acc;
            #pragma unroll 1
            for (int k = 0; k < K; ++k) { acc += sg[k]; g_gam[k + 1] = acc; }
            __threadfence();
            g_flag = 1;                        // release coefficients
        }
        __syncthreads();                       // uni free to be reused as xs
    }

    // ---------- P1: stage x^2 (xs = uni, offset 31) + variance ----------
    float* xs = uni;
    if (td < 31) xs[td] = 0.f;
    if (td < 9)  xs[31 + Sn + td] = 0.f;

    float sum = 0.f, sq = 0.f;
    #pragma unroll
    for (int i = td; i < Sn / 4; i += 256) {
        float4 q = reinterpret_cast<const float4*>(r)[i];
        xs[31 + 4 * i + 0] = q.x * q.x;
        xs[31 + 4 * i + 1] = q.y * q.y;
        xs[31 + 4 * i + 2] = q.z * q.z;
        xs[31 + 4 * i + 3] = q.w * q.w;
        sum += (q.x + q.y) + (q.z + q.w);
        sq = fmaf(q.x, q.x, sq); sq = fmaf(q.y, q.y, sq);
        sq = fmaf(q.z, q.z, sq); sq = fmaf(q.w, q.w, sq);
    }
    #pragma unroll
    for (int o = 16; o; o >>= 1) {
        sum += __shfl_xor_sync(FULLMASK, sum, o);
        sq  += __shfl_xor_sync(FULLMASK, sq, o);
    }
    if ((td & 31) == 0) { rsum[td >> 5] = sum; rsq[td >> 5] = sq; }
    __syncthreads();
    if (td == 0) {
        float S = 0.f, Q = 0.f;
        #pragma unroll
        for (int w = 0; w < 8; ++w) { S += rsum[w]; Q += rsq[w]; }
        out[(size_t)b * Sn] = (Q - S * S * (1.f / Sn)) * (1.f / (Sn - 1));
    }

    // ---------- wait for coefficients (blocks > 0) ----------
    if (b != 0) {
        if (td == 0) {
            while (g_flag == 0) { __nanosleep(64); }
        }
        __syncthreads();
        __threadfence();                       // acquire g_alpha/g_beta/g_gam
    }
    if (td < K)     sal[td]  = g_alpha[td];
    if (td < K + 1) sgam[td] = g_gam[td];
    __syncthreads();

    // ---------- P2: FIR into g_E ----------
    const int i0 = td * 8;
    float w[40];
    #pragma unroll
    for (int m = 0; m < 10; ++m)
        reinterpret_cast<float4*>(w)[m] = *reinterpret_cast<const float4*>(&xs[i0 + 4 * m]);
    float acc[8] = {0.f, 0.f, 0.f, 0.f, 0.f, 0.f, 0.f, 0.f};
    #pragma unroll
    for (int k = 0; k < K; ++k) {
        float a = sal[k];
        #pragma unroll
        for (int i = 0; i < 8; ++i) acc[i] = fmaf(a, w[i + 31 - k], acc[i]);
    }
    #pragma unroll
    for (int i = 0; i < 8; ++i) {
        int t = i0 + i + 1;
        acc[i] = (acc[i] + sgam[min(t, K)]) * LOG2E;
    }
    float* eo = g_E + (size_t)b * Sn + i0;
    reinterpret_cast<float4*>(eo)[0] = make_float4(acc[0], acc[1], acc[2], acc[3]);
    reinterpret_cast<float4*>(eo)[1] = make_float4(acc[4], acc[5], acc[6], acc[7]);

    // ---------- epilogue: last block resets flag for next replay ----------
    __syncthreads();
    if (td == 0) {
        int old = atomicAdd(&g_passed, 1);
        if (old == (int)gridDim.x - 1) {
            g_passed = 0;
            __threadfence();
            g_flag = 0;
        }
    }
}

// ============================================================
// Kernel 2: chunk-parallel scan (unchanged from R7).
// ============================================================
__global__ void __launch_bounds__(128) scan_kernel(float* __restrict__ out) {
    const int gid = blockIdx.x * 128 + threadIdx.x;
    const int b = gid & (Bn - 1);
    const int c = gid >> 11;               // 0..15

    float beta[KS];
    #pragma unroll
    for (int k = 0; k < KS; ++k) beta[k] = g_beta[k];

    const float* Erow = g_E + (size_t)b * Sn;
    float* orow = out + (size_t)b * Sn;

    const int t_start = (c == 0) ? 1 : (c * LCH - WUP);   // === 1 (mod 16)
    const int nb = (c == 0) ? 8 : 12;
    const int qlo = (c == 0) ? 0 : c * LCH;
    const int qhi = c * LCH + LCH;

    float hist[16];
    #pragma unroll
    for (int i = 0; i < 16; ++i) hist[i] = 0.f;
    float sigma = 0.f;
    float q0 = 0.f, q1 = 0.f, q2 = 0.f, q3 = 0.f;
    if (c == 0) { sigma = orow[0]; hist[0] = sigma; q0 = sigma; }

    float4 ea, eb4, ec, ed;
    {
        const float4* ep = reinterpret_cast<const float4*>(Erow + (t_start - 1));
        ea = ep[0]; eb4 = ep[1]; ec = ep[2]; ed = ep[3];
    }

    #pragma unroll 1
    for (int blk = 0; blk < nb; ++blk) {
        const int tb = t_start + 16 * blk;
        const float4* epn = reinterpret_cast<const float4*>(Erow + (tb + 15));
        float4 na = epn[0], nb4_ = epn[1], nc = epn[2], nd = epn[3];
        float ecur[16] = {ea.x, ea.y, ea.z, ea.w, eb4.x, eb4.y, eb4.z, eb4.w,
                          ec.x, ec.y, ec.z, ec.w, ed.x, ed.y, ed.z, ed.w};
        #pragma unroll
        for (int ss = 0; ss < 16; ++ss) {
            const int t = tb + ss;                   // t === 1+ss (mod 16)
            float p0 = 0.f, p1 = 0.f, p2 = 0.f, p3 = ecur[ss];
            #pragma unroll
            for (int k = 1; k < KS; k += 4) p0 = fmaf(beta[k], hist[(ss - k) & 15], p0);
            #pragma unroll
            for (int k = 2; k < KS; k += 4) p1 = fmaf(beta[k], hist[(ss - k) & 15], p1);
            #pragma unroll
            for (int k = 3; k < KS; k += 4) p2 = fmaf(beta[k], hist[(ss - k) & 15], p2);
            #pragma unroll
            for (int k = 4; k < KS; k += 4) p3 = fmaf(beta[k], hist[(ss - k) & 15], p3);
            float rest = (p0 + p1) + (p2 + p3);
            float y = fmaf(beta[0], sigma, rest);    // y = x * log2(e)
            float e;
            asm("ex2.approx.f32 %0, %1;" : "=f"(e) : "f"(y));
            float lg;
            asm("lg2.approx.f32 %0, %1;" : "=f"(lg) : "f"(e + 1.0f));
            sigma = fmaf(lg, LN2, 1e-6f);            // softplus(x) + EPS
            hist[(1 + ss) & 15] = sigma;
            const int tm4 = (1 + ss) & 3;
            if (tm4 == 0)      q0 = sigma;
            else if (tm4 == 1) q1 = sigma;
            else if (tm4 == 2) q2 = sigma;
            else {
                q3 = sigma;
                if (t - 3 >= qlo && t < qhi)
                    *reinterpret_cast<float4*>(orow + (t - 3)) =
                        make_float4(q0, q1, q2, q3);
            }
        }
        ea = na; eb4 = nb4_; ec = nc; ed = nd;
    }
}

extern "C" void kernel_launch(void* const* d_in, const int* in_sizes, int n_in,
                              void* d_out, int out_size) {
    (void)in_sizes; (void)n_in; (void)out_size;
    const float* res = (const float*)d_in[0];
    const float* Wih = (const float*)d_in[1];
    const float* Bih = (const float*)d_in[2];
    const float* Whh = (const float*)d_in[3];
    const float* Bhh = (const float*)d_in[4];
    const float* Fcw = (const float*)d_in[5];
    const float* Fcb = (const float*)d_in[6];
    float* out = (float*)d_out;

    fir_kernel<<<Bn, 256>>>(res, Wih, Bih, Whh, Bhh, Fcw, Fcb, out);
    scan_kernel<<<(Bn * CCH) / 128, 128>>>(out);
}

// round 10
// speedup vs baseline: 1.1859x; 1.1233x over previous
#include <cuda_runtime.h>

#define FULLMASK 0xffffffffu
constexpr int Bn = 2048;
constexpr int Sn = 2048;
constexpr int K  = 20;     // taps for E-FIR / G prefix
constexpr int KS = 12;     // sigma-feedback taps in scan
constexpr int LCH = 64;    // stored steps per chunk (32 chunks/row)
constexpr int SSTR = 17;   // stage stride (odd -> conflict-free STS)
constexpr int EPAD = 2176; // padded E row floats
constexpr float LOG2E = 1.4426950408889634f;
constexpr float LN2   = 0.6931471805599453f;

__device__ float g_E[(size_t)Bn * Sn + 64];
__device__ float g_alpha[K];
__device__ float g_beta[K];                   // pre-scaled by LOG2E
__device__ float g_gam[K + 1];                // prefix sums incl fcb

// ============================================================
// Kernel A: coefficients (as R7; overlapped with fir P1 via PDL).
// ============================================================
__global__ void __launch_bounds__(128) coef_kernel(
        const float* __restrict__ Wih, const float* __restrict__ Bih,
        const float* __restrict__ Whh, const float* __restrict__ Bhh,
        const float* __restrict__ Fcw, const float* __restrict__ Fcb) {
    __shared__ __align__(16) float Ws[64 * 64];
    __shared__ __align__(16) float P[K][64];
    __shared__ __align__(16) float pcur[64];
    __shared__ float red[128];
    __shared__ float uvb[3][64];
    __shared__ float sg[K];
    const int td = threadIdx.x;
    const int j  = td & 63;
    const int h  = td >> 6;

    #pragma unroll
    for (int m = 0; m < 8; ++m)
        reinterpret_cast<float4*>(Ws)[td + 128 * m] =
            reinterpret_cast<const float4*>(Whh)[td + 128 * m];
    if (h == 0) {
        uvb[0][j] = Wih[2 * j];
        uvb[1][j] = Wih[2 * j + 1];
        uvb[2][j] = Bih[j] + Bhh[j];
        float f = Fcw[j];
        P[0][j] = f;
        pcur[j] = f;
    }
    __syncthreads();

    float Wreg[32];
    #pragma unroll
    for (int r = 0; r < 32; ++r) Wreg[r] = Ws[(32 * h + r) * 64 + j];

    #pragma unroll 1
    for (int k = 1; k < K; ++k) {
        const float4* pp = reinterpret_cast<const float4*>(pcur) + 8 * h;
        float a0 = 0.f, a1 = 0.f, a2 = 0.f, a3 = 0.f;
        #pragma unroll
        for (int m = 0; m < 8; ++m) {
            float4 q = pp[m];
            a0 = fmaf(Wreg[4 * m + 0], q.x, a0);
            a1 = fmaf(Wreg[4 * m + 1], q.y, a1);
            a2 = fmaf(Wreg[4 * m + 2], q.z, a2);
            a3 = fmaf(Wreg[4 * m + 3], q.w, a3);
        }
        red[td] = (a0 + a1) + (a2 + a3);
        __syncthreads();
        if (h == 0) {
            float np = red[j] + red[64 + j];
            P[k][j] = np;
            pcur[j] = np;
        }
        __syncthreads();
    }

    if (td < K) {
        const float* Pk = P[td];
        float A = 0.f, B = 0.f, C = 0.f;
        #pragma unroll 8
        for (int m = 0; m < 64; ++m) {
            int jj = (m + td) & 63;
            float p = Pk[jj];
            A = fmaf(p, uvb[0][jj], A);
            B = fmaf(p, uvb[1][jj], B);
            C = fmaf(p, uvb[2][jj], C);
        }
        g_alpha[td] = A;
        g_beta[td]  = B * LOG2E;
        sg[td] = C;
    }
    __syncthreads();
    if (td == 0) {
        float acc = Fcb[0];
        g_gam[0] = acc;
        #pragma unroll 1
        for (int k = 0; k < K; ++k) { acc += sg[k]; g_gam[k + 1] = acc; }
    }
}

// ============================================================
// Kernel B: P1 (x^2 stage + variance, coef-independent) ->
//           cudaGridDependencySynchronize() -> P2 (FIR -> g_E).
// ============================================================
__global__ void __launch_bounds__(256) fir_kernel(const float* __restrict__ res,
                                                  float* __restrict__ out) {
    __shared__ __align__(16) float xs[31 + Sn + 9];
    __shared__ float sal[K];
    __shared__ float sgam[K + 1];
    __shared__ float rsum[8], rsq[8];
    const int b  = blockIdx.x;
    const int td = threadIdx.x;
    const float* r = res + (size_t)b * Sn;

    if (td < 31) xs[td] = 0.f;
    if (td < 9)  xs[31 + Sn + td] = 0.f;

    float sum = 0.f, sq = 0.f;
    #pragma unroll
    for (int i = td; i < Sn / 4; i += 256) {
        float4 q = reinterpret_cast<const float4*>(r)[i];
        xs[31 + 4 * i + 0] = q.x * q.x;
        xs[31 + 4 * i + 1] = q.y * q.y;
        xs[31 + 4 * i + 2] = q.z * q.z;
        xs[31 + 4 * i + 3] = q.w * q.w;
        sum += (q.x + q.y) + (q.z + q.w);
        sq = fmaf(q.x, q.x, sq); sq = fmaf(q.y, q.y, sq);
        sq = fmaf(q.z, q.z, sq); sq = fmaf(q.w, q.w, sq);
    }
    #pragma unroll
    for (int o = 16; o; o >>= 1) {
        sum += __shfl_xor_sync(FULLMASK, sum, o);
        sq  += __shfl_xor_sync(FULLMASK, sq, o);
    }
    if ((td & 31) == 0) { rsum[td >> 5] = sum; rsq[td >> 5] = sq; }
    __syncthreads();
    if (td == 0) {
        float S = 0.f, Q = 0.f;
        #pragma unroll
        for (int w = 0; w < 8; ++w) { S += rsum[w]; Q += rsq[w]; }
        out[(size_t)b * Sn] = (Q - S * S * (1.f / Sn)) * (1.f / (Sn - 1));
    }

    // wait for coef_kernel results (PDL: rest of this kernel overlapped it)
    cudaGridDependencySynchronize();
    if (td < K)     sal[td]  = g_alpha[td];
    if (td < K + 1) sgam[td] = g_gam[td];
    __syncthreads();

    const int i0 = td * 8;
    float w[40];
    #pragma unroll
    for (int m = 0; m < 10; ++m)
        reinterpret_cast<float4*>(w)[m] = *reinterpret_cast<const float4*>(&xs[i0 + 4 * m]);
    float acc[8] = {0.f, 0.f, 0.f, 0.f, 0.f, 0.f, 0.f, 0.f};
    #pragma unroll
    for (int k = 0; k < K; ++k) {
        float a = sal[k];
        #pragma unroll
        for (int i = 0; i < 8; ++i) acc[i] = fmaf(a, w[i + 31 - k], acc[i]);
    }
    #pragma unroll
    for (int i = 0; i < 8; ++i) {
        int t = i0 + i + 1;
        acc[i] = (acc[i] + sgam[min(t, K)]) * LOG2E;
    }
    float* eo = g_E + (size_t)b * Sn + i0;
    reinterpret_cast<float4*>(eo)[0] = make_float4(acc[0], acc[1], acc[2], acc[3]);
    reinterpret_cast<float4*>(eo)[1] = make_float4(acc[4], acc[5], acc[6], acc[7]);
}

// ============================================================
// Kernel C: scan v2. Block = 4 warps = 4 rows; lanes = 32 chunks of one row.
// E row staged coalesced into smem, padded layout P(j)=j+(j>>6)
// (lane stride 65 -> conflict-free). Output staged in stride-17 smem,
// flushed as semi-coalesced float4 STGs.
// t0 = c*64-64; steps s=0..127; t<1 predicated off; t==0 injects sigma0.
// ============================================================
__global__ void __launch_bounds__(128) scan_kernel(float* __restrict__ out) {
    __shared__ __align__(16) float Es[4][EPAD];
    __shared__ float stg[4][32 * SSTR];
    const int lane = threadIdx.x & 31;
    const int w    = threadIdx.x >> 5;
    const int b    = blockIdx.x * 4 + w;
    const float* Erow = g_E + (size_t)b * Sn;
    float* orow = out + (size_t)b * Sn;

    float beta[KS];
    #pragma unroll
    for (int k = 0; k < KS; ++k) beta[k] = g_beta[k];

    // zero front pad region P < 69 (covers all t<1 reads)
    for (int i = lane; i < 69; i += 32) Es[w][i] = 0.f;
    // coalesced stage: element i stored at P(i+68)
    #pragma unroll
    for (int m = 0; m < 16; ++m) {
        float4 q = reinterpret_cast<const float4*>(Erow)[lane + 32 * m];
        int j = 4 * (lane + 32 * m) + 68;
        Es[w][j + (j >> 6)]             = q.x;
        Es[w][(j + 1) + ((j + 1) >> 6)] = q.y;
        Es[w][(j + 2) + ((j + 2) >> 6)] = q.z;
        Es[w][(j + 3) + ((j + 3) >> 6)] = q.w;
    }
    float sigma0 = orow[0];            // variance from fir_kernel
    __syncwarp();

    const int t0 = lane * LCH - 64;
    float hist[16];
    #pragma unroll
    for (int i = 0; i < 16; ++i) hist[i] = 0.f;
    float sigma = 0.f;

    #pragma unroll 1
    for (int tile = 0; tile < 8; ++tile) {
        const int sbase = tile * 16;
        #pragma unroll
        for (int ss = 0; ss < 16; ++ss) {
            const int s = sbase + ss;
            const int t = t0 + s;
            int j = t + 67;                       // index of E[t-1], shifted
            float e = Es[w][j + (j >> 6)];
            float p0 = 0.f, p1 = 0.f, p2 = e;
            #pragma unroll
            for (int k = 1; k < KS; k += 3) p0 = fmaf(beta[k], hist[(ss - 1 - k) & 15], p0);
            #pragma unroll
            for (int k = 2; k < KS; k += 3) p1 = fmaf(beta[k], hist[(ss - 1 - k) & 15], p1);
            #pragma unroll
            for (int k = 3; k < KS; k += 3) p2 = fmaf(beta[k], hist[(ss - 1 - k) & 15], p2);
            float y = fmaf(beta[0], sigma, (p0 + p1) + p2);   // y = x*log2e
            float ex, lg;
            asm("ex2.approx.f32 %0, %1;" : "=f"(ex) : "f"(y));
            asm("lg2.approx.f32 %0, %1;" : "=f"(lg) : "f"(ex + 1.0f));
            float snew = fmaf(lg, LN2, 1e-6f);                // softplus + EPS
            sigma = (t >= 1) ? snew : ((t == 0) ? sigma0 : 0.f);
            hist[ss & 15] = sigma;                // slot = t mod 16 (t0 ≡ 0 mod 16)
            if (tile >= 4) stg[w][lane * SSTR + ss] = sigma;
        }
        if (tile >= 4) {
            __syncwarp();
            const int T = (tile - 4) * 16;
            #pragma unroll
            for (int m = 0; m < 4; ++m) {
                int f = m * 32 + lane;
                int cc = f >> 2, q = f & 3;
                const float* sp = &stg[w][cc * SSTR + 4 * q];
                *reinterpret_cast<float4*>(orow + cc * LCH + T + 4 * q) =
                    make_float4(sp[0], sp[1], sp[2], sp[3]);
            }
            __syncwarp();
        }
    }
}

extern "C" void kernel_launch(void* const* d_in, const int* in_sizes, int n_in,
                              void* d_out, int out_size) {
    (void)in_sizes; (void)n_in; (void)out_size;
    const float* res = (const float*)d_in[0];
    const float* Wih = (const float*)d_in[1];
    const float* Bih = (const float*)d_in[2];
    const float* Whh = (const float*)d_in[3];
    const float* Bhh = (const float*)d_in[4];
    const float* Fcw = (const float*)d_in[5];
    const float* Fcb = (const float*)d_in[6];
    float* out = (float*)d_out;

    coef_kernel<<<1, 128>>>(Wih, Bih, Whh, Bhh, Fcw, Fcb);

    // fir overlaps coef via programmatic dependent launch
    cudaLaunchConfig_t cfg = {};
    cfg.gridDim  = dim3(Bn);
    cfg.blockDim = dim3(256);
    cudaLaunchAttribute attr[1];
    attr[0].id = cudaLaunchAttributeProgrammaticStreamSerialization;
    attr[0].val.programmaticStreamSerializationAllowed = 1;
    cfg.attrs = attr;
    cfg.numAttrs = 1;
    cudaLaunchKernelEx(&cfg, fir_kernel, res, out);

    scan_kernel<<<Bn / 4, 128>>>(out);
}

// round 11
// speedup vs baseline: 1.2481x; 1.0525x over previous
#include <cuda_runtime.h>

#define FULLMASK 0xffffffffu
constexpr int Bn = 2048;
constexpr int Sn = 2048;
constexpr int K  = 16;     // taps for E-FIR / G prefix (tail ~1.6e-4 rel)
constexpr int KS = 12;     // sigma-feedback taps in scan
constexpr int LCH = 64;    // stored steps per chunk (32 chunks/row)
constexpr int SSTR = 17;   // stage stride (odd -> conflict-free STS)
constexpr int EPAD = 2176; // padded E row floats
constexpr float LOG2E = 1.4426950408889634f;
constexpr float LN2   = 0.6931471805599453f;

__device__ float g_E[(size_t)Bn * Sn + 64];
__device__ float g_alpha[K];
__device__ float g_beta[K];                   // pre-scaled by LOG2E
__device__ float g_gam[K + 1];                // prefix sums incl fcb

// ============================================================
// Kernel A: coefficients. 64 threads, double-buffered p,
// ONE barrier per power iteration. Triggers PDL dependents at entry.
// ============================================================
__global__ void __launch_bounds__(64) coef_kernel(
        const float* __restrict__ Wih, const float* __restrict__ Bih,
        const float* __restrict__ Whh, const float* __restrict__ Bhh,
        const float* __restrict__ Fcw, const float* __restrict__ Fcb) {
    cudaTriggerProgrammaticLaunchCompletion();   // let fir launch NOW

    __shared__ __align__(16) float Ws[64 * 64];
    __shared__ __align__(16) float P[K][64];
    __shared__ __align__(16) float pbuf[2][64];
    __shared__ float uvb[3][64];
    __shared__ float sg[K];
    const int j = threadIdx.x;

    // coalesced stage of Whh (64 threads x 64 float4)
    #pragma unroll
    for (int m = 0; m < 16; ++m)
        reinterpret_cast<float4*>(Ws)[j + 64 * m] =
            reinterpret_cast<const float4*>(Whh)[j + 64 * m];
    uvb[0][j] = Wih[2 * j];
    uvb[1][j] = Wih[2 * j + 1];
    uvb[2][j] = Bih[j] + Bhh[j];
    {
        float f = Fcw[j];
        P[0][j] = f;
        pbuf[0][j] = f;
    }
    __syncthreads();

    float Wc[64];                    // Wc[r] = Whh[r][j]; bank = j%32 -> conflict-free
    #pragma unroll
    for (int r = 0; r < 64; ++r) Wc[r] = Ws[r * 64 + j];

    #pragma unroll 1
    for (int k = 1; k < K; ++k) {
        const float4* pp = reinterpret_cast<const float4*>(pbuf[(k - 1) & 1]);
        float a0 = 0.f, a1 = 0.f, a2 = 0.f, a3 = 0.f;
        #pragma unroll
        for (int m = 0; m < 16; ++m) {
            float4 q = pp[m];                    // broadcast LDS.128
            a0 = fmaf(Wc[4 * m + 0], q.x, a0);
            a1 = fmaf(Wc[4 * m + 1], q.y, a1);
            a2 = fmaf(Wc[4 * m + 2], q.z, a2);
            a3 = fmaf(Wc[4 * m + 3], q.w, a3);
        }
        float np = (a0 + a1) + (a2 + a3);
        pbuf[k & 1][j] = np;                     // write buffer not being read
        P[k][j] = np;
        __syncthreads();                         // one barrier per iter
    }

    if (j < K) {                     // one k per thread: 3 dots of length 64
        const float* Pk = P[j];
        float A = 0.f, B = 0.f, C = 0.f;
        #pragma unroll 8
        for (int m = 0; m < 64; ++m) {
            int jj = (m + j) & 63;               // skew: conflict-free
            float p = Pk[jj];
            A = fmaf(p, uvb[0][jj], A);
            B = fmaf(p, uvb[1][jj], B);
            C = fmaf(p, uvb[2][jj], C);
        }
        g_alpha[j] = A;
        g_beta[j]  = B * LOG2E;
        sg[j] = C;
    }
    __syncthreads();
    if (j == 0) {
        float acc = Fcb[0];
        g_gam[0] = acc;
        #pragma unroll 1
        for (int k = 0; k < K; ++k) { acc += sg[k]; g_gam[k + 1] = acc; }
    }
}

// ============================================================
// Kernel B: P1 (x^2 stage + variance, coef-independent, overlaps coef) ->
//           cudaGridDependencySynchronize() -> P2 (FIR -> g_E).
// ============================================================
__global__ void __launch_bounds__(256) fir_kernel(const float* __restrict__ res,
                                                  float* __restrict__ out) {
    __shared__ __align__(16) float xs[31 + Sn + 9];
    __shared__ float sal[K];
    __shared__ float sgam[K + 1];
    __shared__ float rsum[8], rsq[8];
    const int b  = blockIdx.x;
    const int td = threadIdx.x;
    const float* r = res + (size_t)b * Sn;

    if (td < 31) xs[td] = 0.f;
    if (td < 9)  xs[31 + Sn + td] = 0.f;

    float sum = 0.f, sq = 0.f;
    #pragma unroll
    for (int i = td; i < Sn / 4; i += 256) {
        float4 q = reinterpret_cast<const float4*>(r)[i];
        xs[31 + 4 * i + 0] = q.x * q.x;
        xs[31 + 4 * i + 1] = q.y * q.y;
        xs[31 + 4 * i + 2] = q.z * q.z;
        xs[31 + 4 * i + 3] = q.w * q.w;
        sum += (q.x + q.y) + (q.z + q.w);
        sq = fmaf(q.x, q.x, sq); sq = fmaf(q.y, q.y, sq);
        sq = fmaf(q.z, q.z, sq); sq = fmaf(q.w, q.w, sq);
    }
    #pragma unroll
    for (int o = 16; o; o >>= 1) {
        sum += __shfl_xor_sync(FULLMASK, sum, o);
        sq  += __shfl_xor_sync(FULLMASK, sq, o);
    }
    if ((td & 31) == 0) { rsum[td >> 5] = sum; rsq[td >> 5] = sq; }
    __syncthreads();
    if (td == 0) {
        float S = 0.f, Q = 0.f;
        #pragma unroll
        for (int w = 0; w < 8; ++w) { S += rsum[w]; Q += rsq[w]; }
        out[(size_t)b * Sn] = (Q - S * S * (1.f / Sn)) * (1.f / (Sn - 1));
    }

    // wait for coef_kernel completion (P1 above overlapped it)
    cudaGridDependencySynchronize();
    if (td < K)     sal[td]  = g_alpha[td];
    if (td < K + 1) sgam[td] = g_gam[td];
    __syncthreads();

    // FIR: 8 outputs/thread, K=16 -> 23-float window, 6 float4 loads
    const int i0 = td * 8;
    float w[24];
    #pragma unroll
    for (int m = 0; m < 6; ++m)
        reinterpret_cast<float4*>(w)[m] = *reinterpret_cast<const float4*>(&xs[i0 + 16 + 4 * m]);
    float acc[8] = {0.f, 0.f, 0.f, 0.f, 0.f, 0.f, 0.f, 0.f};
    #pragma unroll
    for (int k = 0; k < K; ++k) {
        float a = sal[k];
        #pragma unroll
        for (int i = 0; i < 8; ++i) acc[i] = fmaf(a, w[i + 15 - k], acc[i]);
    }
    #pragma unroll
    for (int i = 0; i < 8; ++i) {
        int t = i0 + i + 1;
        acc[i] = (acc[i] + sgam[min(t, K)]) * LOG2E;
    }
    float* eo = g_E + (size_t)b * Sn + i0;
    reinterpret_cast<float4*>(eo)[0] = make_float4(acc[0], acc[1], acc[2], acc[3]);
    reinterpret_cast<float4*>(eo)[1] = make_float4(acc[4], acc[5], acc[6], acc[7]);
}

// ============================================================
// Kernel C: scan v2 (unchanged from R10). Block = 4 warps = 4 rows;
// lanes = 32 chunks. E staged coalesced into padded smem; output staged
// in stride-17 smem, flushed as semi-coalesced float4 STGs.
// ============================================================
__global__ void __launch_bounds__(128) scan_kernel(float* __restrict__ out) {
    __shared__ __align__(16) float Es[4][EPAD];
    __shared__ float stg[4][32 * SSTR];
    const int lane = threadIdx.x & 31;
    const int w    = threadIdx.x >> 5;
    const int b    = blockIdx.x * 4 + w;
    const float* Erow = g_E + (size_t)b * Sn;
    float* orow = out + (size_t)b * Sn;

    float beta[KS];
    #pragma unroll
    for (int k = 0; k < KS; ++k) beta[k] = g_beta[k];

    for (int i = lane; i < 69; i += 32) Es[w][i] = 0.f;
    #pragma unroll
    for (int m = 0; m < 16; ++m) {
        float4 q = reinterpret_cast<const float4*>(Erow)[lane + 32 * m];
        int j = 4 * (lane + 32 * m) + 68;
        Es[w][j + (j >> 6)]             = q.x;
        Es[w][(j + 1) + ((j + 1) >> 6)] = q.y;
        Es[w][(j + 2) + ((j + 2) >> 6)] = q.z;
        Es[w][(j + 3) + ((j + 3) >> 6)] = q.w;
    }
    float sigma0 = orow[0];
    __syncwarp();

    const int t0 = lane * LCH - 64;
    float hist[16];
    #pragma unroll
    for (int i = 0; i < 16; ++i) hist[i] = 0.f;
    float sigma = 0.f;

    #pragma unroll 1
    for (int tile = 0; tile < 8; ++tile) {
        const int sbase = tile * 16;
        #pragma unroll
        for (int ss = 0; ss < 16; ++ss) {
            const int s = sbase + ss;
            const int t = t0 + s;
            int j = t + 67;
            float e = Es[w][j + (j >> 6)];
            float p0 = 0.f, p1 = 0.f, p2 = e;
            #pragma unroll
            for (int k = 1; k < KS; k += 3) p0 = fmaf(beta[k], hist[(ss - 1 - k) & 15], p0);
            #pragma unroll
            for (int k = 2; k < KS; k += 3) p1 = fmaf(beta[k], hist[(ss - 1 - k) & 15], p1);
            #pragma unroll
            for (int k = 3; k < KS; k += 3) p2 = fmaf(beta[k], hist[(ss - 1 - k) & 15], p2);
            float y = fmaf(beta[0], sigma, (p0 + p1) + p2);   // y = x*log2e
            float ex, lg;
            asm("ex2.approx.f32 %0, %1;" : "=f"(ex) : "f"(y));
            asm("lg2.approx.f32 %0, %1;" : "=f"(lg) : "f"(ex + 1.0f));
            float snew = fmaf(lg, LN2, 1e-6f);
            sigma = (t >= 1) ? snew : ((t == 0) ? sigma0 : 0.f);
            hist[ss & 15] = sigma;
            if (tile >= 4) stg[w][lane * SSTR + ss] = sigma;
        }
        if (tile >= 4) {
            __syncwarp();
            const int T = (tile - 4) * 16;
            #pragma unroll
            for (int m = 0; m < 4; ++m) {
                int f = m * 32 + lane;
                int cc = f >> 2, q = f & 3;
                const float* sp = &stg[w][cc * SSTR + 4 * q];
                *reinterpret_cast<float4*>(orow + cc * LCH + T + 4 * q) =
                    make_float4(sp[0], sp[1], sp[2], sp[3]);
            }
            __syncwarp();
        }
    }
}

extern "C" void kernel_launch(void* const* d_in, const int* in_sizes, int n_in,
                              void* d_out, int out_size) {
    (void)in_sizes; (void)n_in; (void)out_size;
    const float* res = (const float*)d_in[0];
    const float* Wih = (const float*)d_in[1];
    const float* Bih = (const float*)d_in[2];
    const float* Whh = (const float*)d_in[3];
    const float* Bhh = (const float*)d_in[4];
    const float* Fcw = (const float*)d_in[5];
    const float* Fcb = (const float*)d_in[6];
    float* out = (float*)d_out;

    coef_kernel<<<1, 64>>>(Wih, Bih, Whh, Bhh, Fcw, Fcb);

    // fir overlaps coef via programmatic dependent launch
    cudaLaunchConfig_t cfg = {};
    cfg.gridDim  = dim3(Bn);
    cfg.blockDim = dim3(256);
    cudaLaunchAttribute attr[1];
    attr[0].id = cudaLaunchAttributeProgrammaticStreamSerialization;
    attr[0].val.programmaticStreamSerializationAllowed = 1;
    cfg.attrs = attr;
    cfg.numAttrs = 1;
    cudaLaunchKernelEx(&cfg, fir_kernel, res, out);

    scan_kernel<<<Bn / 4, 128>>>(out);
}

// round 12
// speedup vs baseline: 1.3306x; 1.0661x over previous
#include <cuda_runtime.h>

#define FULLMASK 0xffffffffu
constexpr int Bn = 2048;
constexpr int Sn = 2048;
constexpr int K  = 16;     // taps for E-FIR / G prefix
constexpr int KS = 12;     // sigma-feedback taps in scan
constexpr int LCH = 64;    // stored steps per chunk (32 chunks/row)
constexpr int SSTR = 17;   // output stage stride (odd -> conflict-free)
constexpr int RB  = 2176;  // row buffer floats (padded E layout fits: max 2148)
constexpr float LOG2E = 1.4426950408889634f;
constexpr float LN2   = 0.6931471805599453f;

__device__ float g_alpha[K];
__device__ float g_beta[K];                   // pre-scaled by LOG2E
__device__ float g_gam[K + 1];                // prefix sums incl fcb

// ============================================================
// Kernel A: coefficients (R11 version). Triggers PDL dependents at entry.
// ============================================================
__global__ void __launch_bounds__(64) coef_kernel(
        const float* __restrict__ Wih, const float* __restrict__ Bih,
        const float* __restrict__ Whh, const float* __restrict__ Bhh,
        const float* __restrict__ Fcw, const float* __restrict__ Fcb) {
    cudaTriggerProgrammaticLaunchCompletion();   // let fused kernel start NOW

    __shared__ __align__(16) float Ws[64 * 64];
    __shared__ __align__(16) float P[K][64];
    __shared__ __align__(16) float pbuf[2][64];
    __shared__ float uvb[3][64];
    __shared__ float sg[K];
    const int j = threadIdx.x;

    #pragma unroll
    for (int m = 0; m < 16; ++m)
        reinterpret_cast<float4*>(Ws)[j + 64 * m] =
            reinterpret_cast<const float4*>(Whh)[j + 64 * m];
    uvb[0][j] = Wih[2 * j];
    uvb[1][j] = Wih[2 * j + 1];
    uvb[2][j] = Bih[j] + Bhh[j];
    {
        float f = Fcw[j];
        P[0][j] = f;
        pbuf[0][j] = f;
    }
    __syncthreads();

    float Wc[64];                    // Wc[r] = Whh[r][j]
    #pragma unroll
    for (int r = 0; r < 64; ++r) Wc[r] = Ws[r * 64 + j];

    #pragma unroll 1
    for (int k = 1; k < K; ++k) {
        const float4* pp = reinterpret_cast<const float4*>(pbuf[(k - 1) & 1]);
        float a0 = 0.f, a1 = 0.f, a2 = 0.f, a3 = 0.f;
        #pragma unroll
        for (int m = 0; m < 16; ++m) {
            float4 q = pp[m];
            a0 = fmaf(Wc[4 * m + 0], q.x, a0);
            a1 = fmaf(Wc[4 * m + 1], q.y, a1);
            a2 = fmaf(Wc[4 * m + 2], q.z, a2);
            a3 = fmaf(Wc[4 * m + 3], q.w, a3);
        }
        float np = (a0 + a1) + (a2 + a3);
        pbuf[k & 1][j] = np;
        P[k][j] = np;
        __syncthreads();
    }

    if (j < K) {
        const float* Pk = P[j];
        float A = 0.f, B = 0.f, C = 0.f;
        #pragma unroll 8
        for (int m = 0; m < 64; ++m) {
            int jj = (m + j) & 63;
            float p = Pk[jj];
            A = fmaf(p, uvb[0][jj], A);
            B = fmaf(p, uvb[1][jj], B);
            C = fmaf(p, uvb[2][jj], C);
        }
        g_alpha[j] = A;
        g_beta[j]  = B * LOG2E;
        sg[j] = C;
    }
    __syncthreads();
    if (j == 0) {
        float acc = Fcb[0];
        g_gam[0] = acc;
        #pragma unroll 1
        for (int k = 0; k < K; ++k) { acc += sg[k]; g_gam[k + 1] = acc; }
    }
}

// ============================================================
// Kernel B (fused fir+scan): 4 warps = 4 rows, warp-private end to end.
//  P1: stage x^2 at R[w][16+n] (coalesced) + warp variance -> sigma0 (reg)
//  -- cudaGridDependencySynchronize() (P1 overlapped coef via PDL) --
//  P2: in-place FIR, reverse batches; E[i] stored at padded (i+68)+((i+68)>>6)
//  P3: 32 chunk-scans per warp (lane=chunk, LCH=64, warm-up 64); staged stores
// ============================================================
__global__ void __launch_bounds__(128) fused_kernel(const float* __restrict__ res,
                                                    float* __restrict__ out) {
    __shared__ __align__(16) float R[4][RB];
    __shared__ float stg[4][32 * SSTR];
    __shared__ float sal[K];
    __shared__ float sgam[K + 1];
    const int lane = threadIdx.x & 31;
    const int w    = threadIdx.x >> 5;
    const int b    = blockIdx.x * 4 + w;
    const float* r = res + (size_t)b * Sn;
    float* orow = out + (size_t)b * Sn;

    // ---- P1 ----
    if (lane < 16) R[w][lane] = 0.f;             // x^2 front zeros
    float sum = 0.f, sq = 0.f;
    #pragma unroll
    for (int m = 0; m < 16; ++m) {
        float4 q = reinterpret_cast<const float4*>(r)[lane + 32 * m];
        float4 x2 = make_float4(q.x * q.x, q.y * q.y, q.z * q.z, q.w * q.w);
        *reinterpret_cast<float4*>(&R[w][16 + 4 * (lane + 32 * m)]) = x2;
        sum += (q.x + q.y) + (q.z + q.w);
        sq  += (x2.x + x2.y) + (x2.z + x2.w);
    }
    #pragma unroll
    for (int o = 16; o; o >>= 1) {
        sum += __shfl_xor_sync(FULLMASK, sum, o);
        sq  += __shfl_xor_sync(FULLMASK, sq, o);
    }
    const float sigma0 = (sq - sum * sum * (1.f / Sn)) * (1.f / (Sn - 1));
    if (lane == 0) orow[0] = sigma0;

    // ---- coef results become visible here; P1 above overlapped coef ----
    cudaGridDependencySynchronize();
    if (lane < K)     sal[lane]  = g_alpha[lane];   // dup writes (same data) by all warps
    if (lane < K + 1) sgam[lane] = g_gam[lane];
    float beta[KS];
    #pragma unroll
    for (int k = 0; k < KS; ++k) beta[k] = g_beta[k];
    __syncwarp();

    // ---- P2: in-place FIR, reverse batch order ----
    #pragma unroll 1
    for (int m = 3; m >= 0; --m) {
        const int i0 = (m * 32 + lane) * 16;     // 16 outputs per lane-batch
        float win[36];                           // x^2[i0-16 .. i0+19]
        #pragma unroll
        for (int u = 0; u < 9; ++u)
            *reinterpret_cast<float4*>(&win[4 * u]) =
                *reinterpret_cast<const float4*>(&R[w][i0 + 4 * u]);
        __syncwarp();                            // all windows read before any E write
        if (m == 0) {                            // zero E front pad [16,69)
            for (int z = 16 + lane; z < 69; z += 32) R[w][z] = 0.f;
        }
        float acc[16];
        #pragma unroll
        for (int ii = 0; ii < 16; ++ii) acc[ii] = 0.f;
        #pragma unroll
        for (int k = 0; k < K; ++k) {
            float a = sal[k];
            #pragma unroll
            for (int ii = 0; ii < 16; ++ii)
                acc[ii] = fmaf(a, win[ii + 16 - k], acc[ii]);
        }
        #pragma unroll
        for (int ii = 0; ii < 16; ++ii) {
            int i = i0 + ii;                     // E index (t = i+1)
            float e = (acc[ii] + sgam[min(i + 1, K)]) * LOG2E;
            int j = i + 68;
            R[w][j + (j >> 6)] = e;              // padded, conflict-light scatter
        }
        __syncwarp();
    }

    // ---- P3: chunk scans (lane = chunk; t0 = lane*64 - 64) ----
    const int t0 = lane * LCH - 64;
    float hist[16];
    #pragma unroll
    for (int i = 0; i < 16; ++i) hist[i] = 0.f;
    float sigma = 0.f;

    #pragma unroll 1
    for (int tile = 0; tile < 8; ++tile) {
        const int sbase = tile * 16;
        #pragma unroll
        for (int ss = 0; ss < 16; ++ss) {
            const int t = t0 + sbase + ss;
            int j = t + 67;                      // E[t-1] at (t+67)+((t+67)>>6)
            float e = R[w][j + (j >> 6)];
            float p0 = 0.f, p1 = 0.f, p2 = e;
            #pragma unroll
            for (int k = 1; k < KS; k += 3) p0 = fmaf(beta[k], hist[(ss - 1 - k) & 15], p0);
            #pragma unroll
            for (int k = 2; k < KS; k += 3) p1 = fmaf(beta[k], hist[(ss - 1 - k) & 15], p1);
            #pragma unroll
            for (int k = 3; k < KS; k += 3) p2 = fmaf(beta[k], hist[(ss - 1 - k) & 15], p2);
            float y = fmaf(beta[0], sigma, (p0 + p1) + p2);   // y = x*log2e
            float ex, lg;
            asm("ex2.approx.f32 %0, %1;" : "=f"(ex) : "f"(y));
            asm("lg2.approx.f32 %0, %1;" : "=f"(lg) : "f"(ex + 1.0f));
            float snew = fmaf(lg, LN2, 1e-6f);                // softplus + EPS
            sigma = (t >= 1) ? snew : ((t == 0) ? sigma0 : 0.f);
            hist[(sbase + ss) & 15] = sigma;
            if (tile >= 4) stg[w][lane * SSTR + ss] = sigma;
        }
        if (tile >= 4) {
            __syncwarp();
            const int T = (tile - 4) * 16;
            #pragma unroll
            for (int m = 0; m < 4; ++m) {
                int f = m * 32 + lane;
                int cc = f >> 2, q = f & 3;
                const float* sp = &stg[w][cc * SSTR + 4 * q];
                *reinterpret_cast<float4*>(orow + cc * LCH + T + 4 * q) =
                    make_float4(sp[0], sp[1], sp[2], sp[3]);
            }
            __syncwarp();
        }
    }
}

extern "C" void kernel_launch(void* const* d_in, const int* in_sizes, int n_in,
                              void* d_out, int out_size) {
    (void)in_sizes; (void)n_in; (void)out_size;
    const float* res = (const float*)d_in[0];
    const float* Wih = (const float*)d_in[1];
    const float* Bih = (const float*)d_in[2];
    const float* Whh = (const float*)d_in[3];
    const float* Bhh = (const float*)d_in[4];
    const float* Fcw = (const float*)d_in[5];
    const float* Fcb = (const float*)d_in[6];
    float* out = (float*)d_out;

    coef_kernel<<<1, 64>>>(Wih, Bih, Whh, Bhh, Fcw, Fcb);

    cudaLaunchConfig_t cfg = {};
    cfg.gridDim  = dim3(Bn / 4);
    cfg.blockDim = dim3(128);
    cudaLaunchAttribute attr[1];
    attr[0].id = cudaLaunchAttributeProgrammaticStreamSerialization;
    attr[0].val.programmaticStreamSerializationAllowed = 1;
    cfg.attrs = attr;
    cfg.numAttrs = 1;
    cudaLaunchKernelEx(&cfg, fused_kernel, res, out);
}

// round 13
// speedup vs baseline: 1.4217x; 1.0685x over previous
#include <cuda_runtime.h>

#define FULLMASK 0xffffffffu
constexpr int Bn = 2048;
constexpr int Sn = 2048;
constexpr int K  = 16;     // taps for E-FIR / G prefix
constexpr int KS = 10;     // sigma-feedback taps in scan
constexpr int LCH = 32;    // stored steps per chunk (64 chunks/row)
constexpr int WUP = 48;    // warm-up steps (t0 = 32c-48 ≡ 0 mod 16)
constexpr int SSTR = 17;   // stage stride
constexpr float LOG2E = 1.4426950408889634f;
constexpr float LN2   = 0.6931471805599453f;

__device__ float g_alpha[K];
__device__ float g_beta[K];                   // pre-scaled by LOG2E
__device__ float g_gam[K + 1];                // prefix sums incl fcb

// ============================================================
// Kernel A: coefficients (unchanged). Triggers PDL dependents at entry.
// ============================================================
__global__ void __launch_bounds__(64) coef_kernel(
        const float* __restrict__ Wih, const float* __restrict__ Bih,
        const float* __restrict__ Whh, const float* __restrict__ Bhh,
        const float* __restrict__ Fcw, const float* __restrict__ Fcb) {
    cudaTriggerProgrammaticLaunchCompletion();

    __shared__ __align__(16) float Ws[64 * 64];
    __shared__ __align__(16) float P[K][64];
    __shared__ __align__(16) float pbuf[2][64];
    __shared__ float uvb[3][64];
    __shared__ float sg[K];
    const int j = threadIdx.x;

    #pragma unroll
    for (int m = 0; m < 16; ++m)
        reinterpret_cast<float4*>(Ws)[j + 64 * m] =
            reinterpret_cast<const float4*>(Whh)[j + 64 * m];
    uvb[0][j] = Wih[2 * j];
    uvb[1][j] = Wih[2 * j + 1];
    uvb[2][j] = Bih[j] + Bhh[j];
    {
        float f = Fcw[j];
        P[0][j] = f;
        pbuf[0][j] = f;
    }
    __syncthreads();

    float Wc[64];
    #pragma unroll
    for (int r = 0; r < 64; ++r) Wc[r] = Ws[r * 64 + j];

    #pragma unroll 1
    for (int k = 1; k < K; ++k) {
        const float4* pp = reinterpret_cast<const float4*>(pbuf[(k - 1) & 1]);
        float a0 = 0.f, a1 = 0.f, a2 = 0.f, a3 = 0.f;
        #pragma unroll
        for (int m = 0; m < 16; ++m) {
            float4 q = pp[m];
            a0 = fmaf(Wc[4 * m + 0], q.x, a0);
            a1 = fmaf(Wc[4 * m + 1], q.y, a1);
            a2 = fmaf(Wc[4 * m + 2], q.z, a2);
            a3 = fmaf(Wc[4 * m + 3], q.w, a3);
        }
        float np = (a0 + a1) + (a2 + a3);
        pbuf[k & 1][j] = np;
        P[k][j] = np;
        __syncthreads();
    }

    if (j < K) {
        const float* Pk = P[j];
        float A = 0.f, B = 0.f, C = 0.f;
        #pragma unroll 8
        for (int m = 0; m < 64; ++m) {
            int jj = (m + j) & 63;
            float p = Pk[jj];
            A = fmaf(p, uvb[0][jj], A);
            B = fmaf(p, uvb[1][jj], B);
            C = fmaf(p, uvb[2][jj], C);
        }
        g_alpha[j] = A;
        g_beta[j]  = B * LOG2E;
        sg[j] = C;
    }
    __syncthreads();
    if (j == 0) {
        float acc = Fcb[0];
        g_gam[0] = acc;
        #pragma unroll 1
        for (int k = 0; k < K; ++k) { acc += sg[k]; g_gam[k + 1] = acc; }
    }
}

// ============================================================
// Kernel B (fused): 128 thr = 2 rows x 2 warps/row. Per row:
//  P1: both warps stage x^2 halves (coalesced) + joint variance
//  -- cudaGridDependencySynchronize() --
//  P2: each warp FIRs its half into separate padded E buffer
//  P3: 64 chunks (warp h: chunks h*32+lane), LCH=32, WUP=48;
//      output staged in (aliased) smem, flushed as float4 STGs
// ============================================================
__global__ void __launch_bounds__(128) fused_kernel(const float* __restrict__ res,
                                                    float* __restrict__ out) {
    __shared__ __align__(16) float xs[2][2080];    // x^2 at xs[wr][16+n]; aliased by stg in P3
    __shared__ __align__(16) float Epad[2][2176];  // E[i] at (i+52)+((i+52)>>6)
    __shared__ float sal[K];
    __shared__ float sgam[K + 1];
    __shared__ float psum[2][2], psq[2][2];
    const int td   = threadIdx.x;
    const int lane = td & 31;
    const int wid  = td >> 5;        // 0..3
    const int h    = wid & 1;        // half of row
    const int wr   = wid >> 1;       // row in block
    const int b    = blockIdx.x * 2 + wr;
    const float* r = res + (size_t)b * Sn;
    float* orow = out + (size_t)b * Sn;

    // ---- P1: stage x^2 (warp h covers n in [h*1024,(h+1)*1024)) ----
    if (lane < 16 && h == 0) xs[wr][lane] = 0.f;
    float sum = 0.f, sq = 0.f;
    #pragma unroll
    for (int m = 0; m < 8; ++m) {
        int f = h * 256 + lane + 32 * m;
        float4 q = reinterpret_cast<const float4*>(r)[f];
        float4 x2 = make_float4(q.x * q.x, q.y * q.y, q.z * q.z, q.w * q.w);
        *reinterpret_cast<float4*>(&xs[wr][16 + 4 * f]) = x2;
        sum += (q.x + q.y) + (q.z + q.w);
        sq  += (x2.x + x2.y) + (x2.z + x2.w);
    }
    #pragma unroll
    for (int o = 16; o; o >>= 1) {
        sum += __shfl_xor_sync(FULLMASK, sum, o);
        sq  += __shfl_xor_sync(FULLMASK, sq, o);
    }
    if (lane == 0) { psum[wr][h] = sum; psq[wr][h] = sq; }
    // zero Epad front pad [0,52)
    if (td < 52) { Epad[0][td] = 0.f; Epad[1][td] = 0.f; }

    // ---- coef results become visible; P1 overlapped coef via PDL ----
    cudaGridDependencySynchronize();
    if (td < K)     sal[td]  = g_alpha[td];
    if (td < K + 1) sgam[td] = g_gam[td];
    __syncthreads();

    const float S = psum[wr][0] + psum[wr][1];
    const float Q = psq[wr][0] + psq[wr][1];
    const float sigma0 = (Q - S * S * (1.f / Sn)) * (1.f / (Sn - 1));
    float beta[KS];
    #pragma unroll
    for (int k = 0; k < KS; ++k) beta[k] = g_beta[k];

    // ---- P2: FIR; warp h computes E[i], i in [h*1024,(h+1)*1024) ----
    #pragma unroll 1
    for (int m = 0; m < 2; ++m) {
        const int i0 = h * 1024 + (m * 32 + lane) * 16;
        float win[36];                 // win[j] = x^2[i0-16+j]
        #pragma unroll
        for (int u = 0; u < 9; ++u)
            *reinterpret_cast<float4*>(&win[4 * u]) =
                *reinterpret_cast<const float4*>(&xs[wr][i0 + 4 * u]);
        float acc[16];
        #pragma unroll
        for (int ii = 0; ii < 16; ++ii) acc[ii] = 0.f;
        #pragma unroll
        for (int k = 0; k < K; ++k) {
            float a = sal[k];
            #pragma unroll
            for (int ii = 0; ii < 16; ++ii)
                acc[ii] = fmaf(a, win[ii + 16 - k], acc[ii]);
        }
        #pragma unroll
        for (int ii = 0; ii < 16; ++ii) {
            int i = i0 + ii;
            float e = (acc[ii] + sgam[min(i + 1, K)]) * LOG2E;
            int j = i + 52;
            Epad[wr][j + (j >> 6)] = e;
        }
    }
    __syncthreads();                   // E complete (both warps), xs now dead

    // ---- P3: chunk scans. c = h*32+lane, t0 = 32c-48, 5 tiles of 16 ----
    float* stg = &xs[0][0] + wid * (32 * SSTR);   // alias onto dead xs
    const int c  = h * 32 + lane;
    const int t0 = c * LCH - WUP;
    float hist[16];
    #pragma unroll
    for (int i = 0; i < 16; ++i) hist[i] = 0.f;
    float sigma = 0.f;

    #pragma unroll 1
    for (int tile = 0; tile < 5; ++tile) {
        const int sbase = tile * 16;
        #pragma unroll
        for (int ss = 0; ss < 16; ++ss) {
            const int t = t0 + sbase + ss;
            int j = t + 51;                       // E[t-1] at padded (t+51)
            float e = Epad[wr][j + (j >> 6)];
            float p0 = 0.f, p1 = 0.f, p2 = e;
            #pragma unroll
            for (int k = 1; k < KS; k += 3) p0 = fmaf(beta[k], hist[(ss - 1 - k) & 15], p0);
            #pragma unroll
            for (int k = 2; k < KS; k += 3) p1 = fmaf(beta[k], hist[(ss - 1 - k) & 15], p1);
            #pragma unroll
            for (int k = 3; k < KS; k += 3) p2 = fmaf(beta[k], hist[(ss - 1 - k) & 15], p2);
            float y = fmaf(beta[0], sigma, (p0 + p1) + p2);
            float ex, lg;
            asm("ex2.approx.f32 %0, %1;" : "=f"(ex) : "f"(y));
            asm("lg2.approx.f32 %0, %1;" : "=f"(lg) : "f"(ex + 1.0f));
            float snew = fmaf(lg, LN2, 1e-6f);
            sigma = (t >= 1) ? snew : ((t == 0) ? sigma0 : 0.f);
            hist[(sbase + ss) & 15] = sigma;
            if (tile >= 3) stg[lane * SSTR + ss] = sigma;
        }
        if (tile >= 3) {
            __syncwarp();
            const int T = (tile - 3) * 16;
            #pragma unroll
            for (int m = 0; m < 4; ++m) {
                int f = m * 32 + lane;
                int cc = f >> 2, q = f & 3;
                const float* sp = &stg[cc * SSTR + 4 * q];
                *reinterpret_cast<float4*>(orow + (h * 32 + cc) * LCH + T + 4 * q) =
                    make_float4(sp[0], sp[1], sp[2], sp[3]);
            }
            __syncwarp();
        }
    }
}

extern "C" void kernel_launch(void* const* d_in, const int* in_sizes, int n_in,
                              void* d_out, int out_size) {
    (void)in_sizes; (void)n_in; (void)out_size;
    const float* res = (const float*)d_in[0];
    const float* Wih = (const float*)d_in[1];
    const float* Bih = (const float*)d_in[2];
    const float* Whh = (const float*)d_in[3];
    const float* Bhh = (const float*)d_in[4];
    const float* Fcw = (const float*)d_in[5];
    const float* Fcb = (const float*)d_in[6];
    float* out = (float*)d_out;

    coef_kernel<<<1, 64>>>(Wih, Bih, Whh, Bhh, Fcw, Fcb);

    cudaLaunchConfig_t cfg = {};
    cfg.gridDim  = dim3(Bn / 2);
    cfg.blockDim = dim3(128);
    cudaLaunchAttribute attr[1];
    attr[0].id = cudaLaunchAttributeProgrammaticStreamSerialization;
    attr[0].val.programmaticStreamSerializationAllowed = 1;
    cfg.attrs = attr;
    cfg.numAttrs = 1;
    cudaLaunchKernelEx(&cfg, fused_kernel, res, out);
}

// round 14
// speedup vs baseline: 1.4342x; 1.0088x over previous
#include <cuda_runtime.h>

#define FULLMASK 0xffffffffu
constexpr int Bn = 2048;
constexpr int Sn = 2048;
constexpr int K  = 16;     // taps for E-FIR / G prefix
constexpr int KS = 10;     // sigma-feedback taps in scan
constexpr int LCH = 32;    // stored steps per chunk (64 chunks/row)
constexpr int WUP = 48;    // warm-up steps (t0 = 32c-48 ≡ 0 mod 16)
constexpr int SSTR = 17;   // stage stride
constexpr float LOG2E = 1.4426950408889634f;
constexpr float LN2   = 0.6931471805599453f;

__device__ float g_alpha[K];
__device__ float g_beta[K];                   // pre-scaled by LOG2E
__device__ float g_gam[K + 1];                // prefix sums incl fcb

// ============================================================
// Kernel A: coefficients (unchanged). Triggers PDL dependents at entry.
// ============================================================
__global__ void __launch_bounds__(64) coef_kernel(
        const float* __restrict__ Wih, const float* __restrict__ Bih,
        const float* __restrict__ Whh, const float* __restrict__ Bhh,
        const float* __restrict__ Fcw, const float* __restrict__ Fcb) {
    cudaTriggerProgrammaticLaunchCompletion();

    __shared__ __align__(16) float Ws[64 * 64];
    __shared__ __align__(16) float P[K][64];
    __shared__ __align__(16) float pbuf[2][64];
    __shared__ float uvb[3][64];
    __shared__ float sg[K];
    const int j = threadIdx.x;

    #pragma unroll
    for (int m = 0; m < 16; ++m)
        reinterpret_cast<float4*>(Ws)[j + 64 * m] =
            reinterpret_cast<const float4*>(Whh)[j + 64 * m];
    uvb[0][j] = Wih[2 * j];
    uvb[1][j] = Wih[2 * j + 1];
    uvb[2][j] = Bih[j] + Bhh[j];
    {
        float f = Fcw[j];
        P[0][j] = f;
        pbuf[0][j] = f;
    }
    __syncthreads();

    float Wc[64];
    #pragma unroll
    for (int r = 0; r < 64; ++r) Wc[r] = Ws[r * 64 + j];

    #pragma unroll 1
    for (int k = 1; k < K; ++k) {
        const float4* pp = reinterpret_cast<const float4*>(pbuf[(k - 1) & 1]);
        float a0 = 0.f, a1 = 0.f, a2 = 0.f, a3 = 0.f;
        #pragma unroll
        for (int m = 0; m < 16; ++m) {
            float4 q = pp[m];
            a0 = fmaf(Wc[4 * m + 0], q.x, a0);
            a1 = fmaf(Wc[4 * m + 1], q.y, a1);
            a2 = fmaf(Wc[4 * m + 2], q.z, a2);
            a3 = fmaf(Wc[4 * m + 3], q.w, a3);
        }
        float np = (a0 + a1) + (a2 + a3);
        pbuf[k & 1][j] = np;
        P[k][j] = np;
        __syncthreads();
    }

    if (j < K) {
        const float* Pk = P[j];
        float A = 0.f, B = 0.f, C = 0.f;
        #pragma unroll 8
        for (int m = 0; m < 64; ++m) {
            int jj = (m + j) & 63;
            float p = Pk[jj];
            A = fmaf(p, uvb[0][jj], A);
            B = fmaf(p, uvb[1][jj], B);
            C = fmaf(p, uvb[2][jj], C);
        }
        g_alpha[j] = A;
        g_beta[j]  = B * LOG2E;
        sg[j] = C;
    }
    __syncthreads();
    if (j == 0) {
        float acc = Fcb[0];
        g_gam[0] = acc;
        #pragma unroll 1
        for (int k = 0; k < K; ++k) { acc += sg[k]; g_gam[k + 1] = acc; }
    }
}

// ============================================================
// Kernel B (fused, in-place): 128 thr = 2 rows x 2 warps/row.
//  P1: stage x^2 at xs[wr][16+n] (coalesced) + joint variance
//  -- cudaGridDependencySynchronize() --
//  P2: IN-PLACE FIR into xs. E[i] at p=(i+52)+((i+52)>>5).
//      Two steps, descending write regions:
//        step0: warp0 B=1536 (writes p 1637..2164), warp1 B=1024 (p 1109..1636)
//        step1: warp0 B=512  (p 581..1108),        warp1 B=0    (p 53..580)
//      reads of step1 (xs <=1059) < step0 writes (>=1109): safe.
//  P3: 64 chunks (c = h*32+lane), LCH=32, WUP=48; conflict-free E reads
//      (lane stride 33); staged stores.
// ============================================================
__global__ void __launch_bounds__(128, 7) fused_kernel(const float* __restrict__ res,
                                                       float* __restrict__ out) {
    __shared__ __align__(16) float xs[2][2176];
    __shared__ float stg[4][32 * SSTR];
    __shared__ float sal[K];
    __shared__ float sgam[K + 1];
    __shared__ float psum[2][2], psq[2][2];
    const int td   = threadIdx.x;
    const int lane = td & 31;
    const int wid  = td >> 5;
    const int h    = wid & 1;
    const int wr   = wid >> 1;
    const int b    = blockIdx.x * 2 + wr;
    const float* r = res + (size_t)b * Sn;
    float* orow = out + (size_t)b * Sn;

    // ---- P1 ----
    if (lane < 16 && h == 0) xs[wr][lane] = 0.f;
    float sum = 0.f, sq = 0.f;
    #pragma unroll
    for (int m = 0; m < 8; ++m) {
        int f = h * 256 + lane + 32 * m;
        float4 q = reinterpret_cast<const float4*>(r)[f];
        float4 x2 = make_float4(q.x * q.x, q.y * q.y, q.z * q.z, q.w * q.w);
        *reinterpret_cast<float4*>(&xs[wr][16 + 4 * f]) = x2;
        sum += (q.x + q.y) + (q.z + q.w);
        sq  += (x2.x + x2.y) + (x2.z + x2.w);
    }
    #pragma unroll
    for (int o = 16; o; o >>= 1) {
        sum += __shfl_xor_sync(FULLMASK, sum, o);
        sq  += __shfl_xor_sync(FULLMASK, sq, o);
    }
    if (lane == 0) { psum[wr][h] = sum; psq[wr][h] = sq; }

    // ---- coef results become visible; P1 overlapped coef via PDL ----
    cudaGridDependencySynchronize();
    if (td < K)     sal[td]  = g_alpha[td];
    if (td < K + 1) sgam[td] = g_gam[td];
    __syncthreads();

    const float S = psum[wr][0] + psum[wr][1];
    const float Q = psq[wr][0] + psq[wr][1];
    const float sigma0 = (Q - S * S * (1.f / Sn)) * (1.f / (Sn - 1));
    if (lane == 0 && h == 0) orow[0] = sigma0;
    float beta[KS];
    #pragma unroll
    for (int k = 0; k < KS; ++k) beta[k] = g_beta[k];

    // ---- P2: in-place FIR, two descending steps ----
    #pragma unroll 1
    for (int step = 0; step < 2; ++step) {
        const int B = (step == 0) ? (1536 - 512 * h) : (512 - 512 * h);
        const int i0 = B + lane * 16;
        float win[36];                       // win[u] = x^2[i0-16+u] = xs[i0+u]
        #pragma unroll
        for (int u = 0; u < 9; ++u)
            *reinterpret_cast<float4*>(&win[4 * u]) =
                *reinterpret_cast<const float4*>(&xs[wr][i0 + 4 * u]);
        __syncthreads();                     // all reads done before any write
        float acc[16];
        #pragma unroll
        for (int ii = 0; ii < 16; ++ii) acc[ii] = 0.f;
        #pragma unroll
        for (int k = 0; k < K; ++k) {
            float a = sal[k];
            #pragma unroll
            for (int ii = 0; ii < 16; ++ii)
                acc[ii] = fmaf(a, win[ii + 16 - k], acc[ii]);
        }
        #pragma unroll
        for (int ii = 0; ii < 16; ++ii) {
            int i = i0 + ii;
            float e = (acc[ii] + sgam[min(i + 1, K)]) * LOG2E;
            int j = i + 52;
            xs[wr][j + (j >> 5)] = e;
        }
        if (step == 1 && h == 0) {           // zero E front pad [0,53)
            for (int z = lane; z < 53; z += 32) xs[wr][z] = 0.f;
        }
        __syncthreads();
    }

    // ---- P3: chunk scans. c = h*32+lane, t0 = 32c-48, 5 tiles of 16 ----
    float* stgw = stg[wid];
    const int c  = h * 32 + lane;
    const int t0 = c * LCH - WUP;
    float hist[16];
    #pragma unroll
    for (int i = 0; i < 16; ++i) hist[i] = 0.f;
    float sigma = 0.f;

    #pragma unroll 1
    for (int tile = 0; tile < 5; ++tile) {
        const int sbase = tile * 16;
        #pragma unroll
        for (int ss = 0; ss < 16; ++ss) {
            const int t = t0 + sbase + ss;
            int j = t + 51;                  // E[t-1] at p = j + (j>>5)
            float e = xs[wr][j + (j >> 5)];
            float p0 = 0.f, p1 = 0.f, p2 = e;
            #pragma unroll
            for (int k = 1; k < KS; k += 3) p0 = fmaf(beta[k], hist[(ss - 1 - k) & 15], p0);
            #pragma unroll
            for (int k = 2; k < KS; k += 3) p1 = fmaf(beta[k], hist[(ss - 1 - k) & 15], p1);
            #pragma unroll
            for (int k = 3; k < KS; k += 3) p2 = fmaf(beta[k], hist[(ss - 1 - k) & 15], p2);
            float y = fmaf(beta[0], sigma, (p0 + p1) + p2);
            float ex, lg;
            asm("ex2.approx.f32 %0, %1;" : "=f"(ex) : "f"(y));
            asm("lg2.approx.f32 %0, %1;" : "=f"(lg) : "f"(ex + 1.0f));
            float snew = fmaf(lg, LN2, 1e-6f);
            sigma = (t >= 1) ? snew : ((t == 0) ? sigma0 : 0.f);
            hist[ss] = sigma;                // slot = t mod 16 (t0 ≡ 0 mod 16)
            if (tile >= 3) stgw[lane * SSTR + ss] = sigma;
        }
        if (tile >= 3) {
            __syncwarp();
            const int T = (tile - 3) * 16;
            #pragma unroll
            for (int m = 0; m < 4; ++m) {
                int f = m * 32 + lane;
                int cc = f >> 2, q = f & 3;
                const float* sp = &stgw[cc * SSTR + 4 * q];
                *reinterpret_cast<float4*>(orow + (h * 32 + cc) * LCH + T + 4 * q) =
                    make_float4(sp[0], sp[1], sp[2], sp[3]);
            }
            __syncwarp();
        }
    }
}

extern "C" void kernel_launch(void* const* d_in, const int* in_sizes, int n_in,
                              void* d_out, int out_size) {
    (void)in_sizes; (void)n_in; (void)out_size;
    const float* res = (const float*)d_in[0];
    const float* Wih = (const float*)d_in[1];
    const float* Bih = (const float*)d_in[2];
    const float* Whh = (const float*)d_in[3];
    const float* Bhh = (const float*)d_in[4];
    const float* Fcw = (const float*)d_in[5];
    const float* Fcb = (const float*)d_in[6];
    float* out = (float*)d_out;

    coef_kernel<<<1, 64>>>(Wih, Bih, Whh, Bhh, Fcw, Fcb);

    cudaLaunchConfig_t cfg = {};
    cfg.gridDim  = dim3(Bn / 2);
    cfg.blockDim = dim3(128);
    cudaLaunchAttribute attr[1];
    attr[0].id = cudaLaunchAttributeProgrammaticStreamSerialization;
    attr[0].val.programmaticStreamSerializationAllowed = 1;
    cfg.attrs = attr;
    cfg.numAttrs = 1;
    cudaLaunchKernelEx(&cfg, fused_kernel, res, out);
}